// round 1
// baseline (speedup 1.0000x reference)
#include <cuda_runtime.h>
#include <cuda_fp16.h>
#include <cstdint>

#define N_GENES 16384
#define N_REG   8192
#define D_MODEL 256
#define OUT_DIM 128
#define ALPHA   0.2f

#define TI 64     // regulon rows per block
#define TJ 64     // j tile

// ---------------- device scratch (no allocations allowed) ----------------
__device__ float  g_wh [N_GENES * OUT_DIM];                    // fp32 w_h
__device__ __align__(16) __half g_whh[N_GENES * OUT_DIM];      // fp16 w_h (V)
__device__ float  g_wh1[N_REG];
__device__ float  g_wh2[N_GENES];
__device__ float  g_F1 [N_GENES];   // exp(wh2)
__device__ float  g_F2 [N_GENES];   // exp(alpha*wh2)
__device__ float  g_G1 [N_REG];     // exp(wh1 - B)
__device__ float  g_G2 [N_REG];     // exp(alpha*wh1 - B)
__device__ float  g_w2max;

// ---------------- K1: w_h = input @ weights  ----------------
__global__ void k_gemm1(const float* __restrict__ inp, const float* __restrict__ W) {
    __shared__ float s_in[8][D_MODEL];
    const int c  = threadIdx.x;          // 0..127 output column
    const int r0 = blockIdx.x * 8;
    for (int idx = c; idx < 8 * D_MODEL; idx += 128)
        s_in[idx >> 8][idx & 255] = inp[(size_t)(r0 + (idx >> 8)) * D_MODEL + (idx & 255)];
    __syncthreads();
    float acc[8] = {0.f,0.f,0.f,0.f,0.f,0.f,0.f,0.f};
    #pragma unroll 4
    for (int k = 0; k < D_MODEL; k++) {
        float w = W[k * OUT_DIM + c];
        #pragma unroll
        for (int r = 0; r < 8; r++) acc[r] = fmaf(s_in[r][k], w, acc[r]);
    }
    #pragma unroll
    for (int r = 0; r < 8; r++) {
        float v = acc[r];
        g_wh [(size_t)(r0 + r) * OUT_DIM + c] = v;
        g_whh[(size_t)(r0 + r) * OUT_DIM + c] = __float2half(v);
    }
}

// ---------------- K2: wh1, wh2 (one warp per row) ----------------
__global__ void k_wh12(const float* __restrict__ a) {
    const int row  = blockIdx.x * 8 + (threadIdx.x >> 5);
    const int lane = threadIdx.x & 31;
    const float* r = g_wh + (size_t)row * OUT_DIM;
    float s1 = 0.f, s2 = 0.f;
    #pragma unroll
    for (int c = lane; c < OUT_DIM; c += 32) {
        float v = r[c];
        s1 = fmaf(v, a[c], s1);
        s2 = fmaf(v, a[OUT_DIM + c], s2);
    }
    #pragma unroll
    for (int o = 16; o; o >>= 1) {
        s1 += __shfl_xor_sync(0xffffffffu, s1, o);
        s2 += __shfl_xor_sync(0xffffffffu, s2, o);
    }
    if (lane == 0) {
        if (row < N_REG) g_wh1[row] = s1;
        g_wh2[row] = s2;
    }
}

// ---------------- K3: max over wh2 (single block) ----------------
__global__ void k_max() {
    __shared__ float sm[32];
    float m = -1e30f;
    for (int j = threadIdx.x; j < N_GENES; j += blockDim.x) m = fmaxf(m, g_wh2[j]);
    #pragma unroll
    for (int o = 16; o; o >>= 1) m = fmaxf(m, __shfl_xor_sync(0xffffffffu, m, o));
    if ((threadIdx.x & 31) == 0) sm[threadIdx.x >> 5] = m;
    __syncthreads();
    if (threadIdx.x < 32) {
        float v = (threadIdx.x < (blockDim.x >> 5)) ? sm[threadIdx.x] : -1e30f;
        #pragma unroll
        for (int o = 16; o; o >>= 1) v = fmaxf(v, __shfl_xor_sync(0xffffffffu, v, o));
        if (threadIdx.x == 0) g_w2max = v;
    }
}

// ---------------- K4: exp factor tables ----------------
__global__ void k_factors() {
    const int j = blockIdx.x * 256 + threadIdx.x;
    const float w2m = g_w2max;
    if (j < N_GENES) {
        float w2 = g_wh2[j];
        g_F1[j] = expf(w2);
        g_F2[j] = expf(ALPHA * w2);
    }
    if (j < N_REG) {
        float w1 = g_wh1[j];
        float x  = w1 + w2m;
        float B  = x > 0.f ? x : ALPHA * x;   // upper bound of e over the row
        g_G1[j] = expf(w1 - B);
        g_G2[j] = expf(ALPHA * w1 - B);
    }
}

// ---------------- K5: fused masked-softmax-attention (single pass over adj) ----------------
__device__ __forceinline__ uint32_t smem_u32(const void* p) {
    return (uint32_t)__cvta_generic_to_shared(p);
}

__global__ void __launch_bounds__(512)
k_attn(const float* __restrict__ adj, float* __restrict__ out) {
    __shared__ __align__(16) __half sP[TI][TJ + 8];           // P tile (fp16)
    __shared__ __align__(16) __half sV[TJ][OUT_DIM + 8];      // V tile (fp16)
    __shared__ float sSp[16][8];
    __shared__ float sInv[TI];

    const int t    = threadIdx.x;
    const int lane = t & 31;
    const int warp = t >> 5;          // 0..15
    const int i0   = blockIdx.x * TI;
    const int jl   = t & 63;          // thread's j within tile
    const int oct  = t >> 6;          // 8 rows per octant

    // per-thread row constants (8 rows of the octant)
    float Tr[8], G1r[8], G2r[8], sacc[8];
    #pragma unroll
    for (int r = 0; r < 8; r++) {
        const int i = i0 + oct * 8 + r;
        Tr[r]  = g_wh1[i];
        G1r[r] = g_G1[i];
        G2r[r] = g_G2[i];
        sacc[r] = 0.f;
    }

    // mma accumulators: warp covers 16 rows x 32 cols -> 4 n-tiles x 4 regs
    float d[4][4];
    #pragma unroll
    for (int n = 0; n < 4; n++)
        #pragma unroll
        for (int k = 0; k < 4; k++) d[n][k] = 0.f;

    const int wi = warp >> 2;   // 0..3 : rows wi*16
    const int wc = warp & 3;    // 0..3 : cols wc*32

    // prefetch registers
    float adjv[8];
    float w2v, f1v, f2v;
    uint4 vv[2];

    auto prefetch = [&](int jt) {
        const int j0 = jt * TJ;
        const int j  = j0 + jl;
        #pragma unroll
        for (int r = 0; r < 8; r++)
            adjv[r] = __ldg(&adj[(size_t)(i0 + oct * 8 + r) * N_GENES + j]);
        w2v = g_wh2[j];
        f1v = g_F1[j];
        f2v = g_F2[j];
        #pragma unroll
        for (int u = 0; u < 2; u++) {
            const int lin = t + u * 512;       // 0..1023 -> 1024 uint4 of V tile
            const int jr = lin >> 4, cq = lin & 15;
            vv[u] = *reinterpret_cast<const uint4*>(&g_whh[(size_t)(j0 + jr) * OUT_DIM + cq * 8]);
        }
    };

    prefetch(0);

    const int NT = N_GENES / TJ;   // 256
    for (int jt = 0; jt < NT; jt++) {
        __syncthreads();   // previous mma done reading smem
        // stage V tile
        #pragma unroll
        for (int u = 0; u < 2; u++) {
            const int lin = t + u * 512;
            const int jr = lin >> 4, cq = lin & 15;
            *reinterpret_cast<uint4*>(&sV[jr][cq * 8]) = vv[u];
        }
        // build P column jl for 8 rows (unnormalized softmax, row-bounded <= 1)
        #pragma unroll
        for (int r = 0; r < 8; r++) {
            float x = Tr[r] + w2v;
            float a = adjv[r];
            float q = (x > 0.f) ? (G1r[r] * f1v) : (G2r[r] * f2v);
            float p = (a != 0.f && x != 0.f) ? q : 0.f;
            sacc[r] += p;
            sP[oct * 8 + r][jl] = __float2half(p);
        }
        if (jt + 1 < NT) prefetch(jt + 1);   // hide HBM latency under mma phase
        __syncthreads();

        // MMA: 64x128 += Ptile(64x64) @ Vtile(64x128)
        #pragma unroll
        for (int ks = 0; ks < 4; ks++) {
            uint32_t a0, a1, a2, a3;
            uint32_t aaddr = smem_u32(&sP[wi * 16 + (lane & 15)][ks * 16 + (lane >> 4) * 8]);
            asm volatile("ldmatrix.sync.aligned.m8n8.x4.shared.b16 {%0,%1,%2,%3},[%4];\n"
                         : "=r"(a0), "=r"(a1), "=r"(a2), "=r"(a3) : "r"(aaddr));
            uint32_t b[8];
            uint32_t baddr0 = smem_u32(&sV[ks * 16 + (lane & 15)][wc * 32 + (lane >> 4) * 8]);
            asm volatile("ldmatrix.sync.aligned.m8n8.x4.trans.shared.b16 {%0,%1,%2,%3},[%4];\n"
                         : "=r"(b[0]), "=r"(b[1]), "=r"(b[2]), "=r"(b[3]) : "r"(baddr0));
            uint32_t baddr1 = smem_u32(&sV[ks * 16 + (lane & 15)][wc * 32 + 16 + (lane >> 4) * 8]);
            asm volatile("ldmatrix.sync.aligned.m8n8.x4.trans.shared.b16 {%0,%1,%2,%3},[%4];\n"
                         : "=r"(b[4]), "=r"(b[5]), "=r"(b[6]), "=r"(b[7]) : "r"(baddr1));
            #pragma unroll
            for (int n = 0; n < 4; n++) {
                asm volatile(
                    "mma.sync.aligned.m16n8k16.row.col.f32.f16.f16.f32 "
                    "{%0,%1,%2,%3},{%4,%5,%6,%7},{%8,%9},{%0,%1,%2,%3};\n"
                    : "+f"(d[n][0]), "+f"(d[n][1]), "+f"(d[n][2]), "+f"(d[n][3])
                    : "r"(a0), "r"(a1), "r"(a2), "r"(a3), "r"(b[n * 2]), "r"(b[n * 2 + 1]));
            }
        }
    }

    // ---- S reduction: 64 threads of an octant-pair share 8 rows ----
    #pragma unroll
    for (int r = 0; r < 8; r++) {
        float v = sacc[r];
        #pragma unroll
        for (int o = 16; o; o >>= 1) v += __shfl_xor_sync(0xffffffffu, v, o);
        if (lane == 0) sSp[warp][r] = v;
    }
    __syncthreads();
    if (t < TI) {
        const int o8 = t >> 3, r = t & 7;
        float S = sSp[o8 * 2][r] + sSp[o8 * 2 + 1][r];
        sInv[t] = 1.0f / S;
    }
    __syncthreads();

    // ---- epilogue: normalize + ELU ----
    #pragma unroll
    for (int n = 0; n < 4; n++) {
        const int c  = wc * 32 + n * 8 + (lane & 3) * 2;
        const int r1 = wi * 16 + (lane >> 2);
        const float inv1 = sInv[r1], inv2 = sInv[r1 + 8];
        float v00 = d[n][0] * inv1, v01 = d[n][1] * inv1;
        float v10 = d[n][2] * inv2, v11 = d[n][3] * inv2;
        out[(size_t)(i0 + r1) * OUT_DIM + c]         = v00 > 0.f ? v00 : expm1f(v00);
        out[(size_t)(i0 + r1) * OUT_DIM + c + 1]     = v01 > 0.f ? v01 : expm1f(v01);
        out[(size_t)(i0 + r1 + 8) * OUT_DIM + c]     = v10 > 0.f ? v10 : expm1f(v10);
        out[(size_t)(i0 + r1 + 8) * OUT_DIM + c + 1] = v11 > 0.f ? v11 : expm1f(v11);
    }
}

// ---------------- launch ----------------
extern "C" void kernel_launch(void* const* d_in, const int* in_sizes, int n_in,
                              void* d_out, int out_size) {
    const float* inp = (const float*)d_in[0];   // [16384, 256]
    const float* adj = (const float*)d_in[1];   // [8192, 16384]
    const float* W   = (const float*)d_in[2];   // [256, 128]
    const float* a   = (const float*)d_in[3];   // [256, 1]
    float* out = (float*)d_out;                 // [8192, 128]

    k_gemm1  <<<N_GENES / 8,  128>>>(inp, W);
    k_wh12   <<<N_GENES / 8,  256>>>(a);
    k_max    <<<1,           1024>>>();
    k_factors<<<N_GENES / 256, 256>>>();
    k_attn   <<<N_REG / TI,   512>>>(adj, out);
}

// round 3
// speedup vs baseline: 1.0048x; 1.0048x over previous
#include <cuda_runtime.h>
#include <cuda_fp16.h>
#include <cstdint>

#define N_GENES 16384
#define N_REG   8192
#define D_MODEL 256
#define OUT_DIM 128
#define ALPHA   0.2f

#define TI 64                  // regulon rows per CTA
#define TJ 64                  // j per tile (MMA K)
#define NT (N_GENES / TJ)      // 256 tiles

// dynamic smem: P double-buffer 2x8KB, V double-buffer 2x16KB, S 64 floats
#define SM_P0 0
#define SM_P1 8192
#define SM_V0 16384
#define SM_V1 32768
#define SM_S  49152
#define SMEM_BYTES 49664

// ---------------- device scratch ----------------
__device__ float  g_wh [N_GENES * OUT_DIM];
__device__ __align__(16) __half g_whh[N_GENES * OUT_DIM];   // w_h fp16, row-major
__device__ float  g_WT [OUT_DIM * D_MODEL];                 // W^T for gemm1
__device__ float  g_wh1[N_REG];
__device__ float  g_wh2[N_GENES];
__device__ float  g_F1 [N_GENES];
__device__ float  g_F2 [N_GENES];
__device__ float  g_G1 [N_REG];
__device__ float  g_G2 [N_REG];
__device__ float  g_w2max;

// ---------------- helpers ----------------
static __device__ __forceinline__ uint32_t swz(uint32_t x) { return x ^ ((x >> 3) & 0x70); }
static __device__ __forceinline__ uint32_t smem_u32(const void* p) {
    return (uint32_t)__cvta_generic_to_shared(p);
}
static __device__ __forceinline__ uint64_t pk2(float x, float y) {
    uint64_t r; asm("mov.b64 %0, {%1, %2};" : "=l"(r) : "f"(x), "f"(y)); return r;
}
static __device__ __forceinline__ void fma2(uint64_t& acc, uint64_t a, uint64_t b) {
    asm volatile("fma.rn.f32x2 %0, %1, %2, %0;" : "+l"(acc) : "l"(a), "l"(b));
}

// ---------------- K0: W transpose ----------------
__global__ void k_transW(const float* __restrict__ W) {
    g_WT[threadIdx.x * D_MODEL + blockIdx.x] = W[blockIdx.x * OUT_DIM + threadIdx.x];
}

// ---------------- K1: w_h = input @ weights ----------------
__global__ void k_gemm1(const float* __restrict__ inp) {
    __shared__ __align__(16) float s_in[8][D_MODEL];
    const int c  = threadIdx.x;
    const int r0 = blockIdx.x * 8;
    for (int idx = c; idx < 8 * D_MODEL; idx += 128)
        s_in[idx >> 8][idx & 255] = inp[(size_t)(r0 + (idx >> 8)) * D_MODEL + (idx & 255)];
    __syncthreads();

    uint64_t acc[8];
    #pragma unroll
    for (int r = 0; r < 8; r++) acc[r] = 0ull;

    const float4* wt4 = (const float4*)&g_WT[c * D_MODEL];
    #pragma unroll 2
    for (int k4 = 0; k4 < D_MODEL / 4; k4++) {
        float4 wv = __ldg(&wt4[k4]);
        uint64_t w01 = pk2(wv.x, wv.y);
        uint64_t w23 = pk2(wv.z, wv.w);
        #pragma unroll
        for (int r = 0; r < 8; r++) {
            ulonglong2 a2 = *(const ulonglong2*)&s_in[r][k4 * 4];
            fma2(acc[r], a2.x, w01);
            fma2(acc[r], a2.y, w23);
        }
    }
    #pragma unroll
    for (int r = 0; r < 8; r++) {
        float lo = __uint_as_float((uint32_t)acc[r]);
        float hi = __uint_as_float((uint32_t)(acc[r] >> 32));
        float v = lo + hi;
        g_wh [(size_t)(r0 + r) * OUT_DIM + c] = v;
        g_whh[(size_t)(r0 + r) * OUT_DIM + c] = __float2half(v);
    }
}

// ---------------- K2: wh1, wh2 ----------------
__global__ void k_wh12(const float* __restrict__ a) {
    const int row  = blockIdx.x * 8 + (threadIdx.x >> 5);
    const int lane = threadIdx.x & 31;
    const float* r = g_wh + (size_t)row * OUT_DIM;
    float s1 = 0.f, s2 = 0.f;
    #pragma unroll
    for (int c = lane; c < OUT_DIM; c += 32) {
        float v = r[c];
        s1 = fmaf(v, a[c], s1);
        s2 = fmaf(v, a[OUT_DIM + c], s2);
    }
    #pragma unroll
    for (int o = 16; o; o >>= 1) {
        s1 += __shfl_xor_sync(0xffffffffu, s1, o);
        s2 += __shfl_xor_sync(0xffffffffu, s2, o);
    }
    if (lane == 0) {
        if (row < N_REG) g_wh1[row] = s1;
        g_wh2[row] = s2;
    }
}

// ---------------- K3: max over wh2 ----------------
__global__ void k_max() {
    __shared__ float sm[32];
    float m = -1e30f;
    for (int j = threadIdx.x; j < N_GENES; j += blockDim.x) m = fmaxf(m, g_wh2[j]);
    #pragma unroll
    for (int o = 16; o; o >>= 1) m = fmaxf(m, __shfl_xor_sync(0xffffffffu, m, o));
    if ((threadIdx.x & 31) == 0) sm[threadIdx.x >> 5] = m;
    __syncthreads();
    if (threadIdx.x < 32) {
        float v = (threadIdx.x < (blockDim.x >> 5)) ? sm[threadIdx.x] : -1e30f;
        #pragma unroll
        for (int o = 16; o; o >>= 1) v = fmaxf(v, __shfl_xor_sync(0xffffffffu, v, o));
        if (threadIdx.x == 0) g_w2max = v;
    }
}

// ---------------- K4: exp factor tables ----------------
__global__ void k_factors() {
    const int j = blockIdx.x * 256 + threadIdx.x;
    const float w2m = g_w2max;
    if (j < N_GENES) {
        float w2 = g_wh2[j];
        g_F1[j] = expf(w2);
        g_F2[j] = expf(ALPHA * w2);
    }
    if (j < N_REG) {
        float w1 = g_wh1[j];
        float x  = w1 + w2m;
        float B  = x > 0.f ? x : ALPHA * x;
        g_G1[j] = expf(w1 - B);
        g_G2[j] = expf(ALPHA * w1 - B);
    }
}

// ---------------- K5: fused masked-softmax attention (HMMA, single adj pass) ----------------
__global__ void __launch_bounds__(512, 1)
k_attn(const float* __restrict__ adj, float* __restrict__ out) {
    extern __shared__ char smem[];
    const uint32_t sb = smem_u32(smem);
    float* sS = (float*)(smem + SM_S);

    const int t    = threadIdx.x;
    const int lane = t & 31, warp = t >> 5;
    const int i0   = blockIdx.x * TI;
    const int jp   = lane;            // column pair: cols jp*2, jp*2+1
    const int wg   = warp;            // P-build rows wg*4 .. wg*4+3

    // per-thread row constants for P build (4 rows)
    float Tr[4], G1r[4], G2r[4], sacc[4];
    #pragma unroll
    for (int r = 0; r < 4; r++) {
        const int i = i0 + wg * 4 + r;
        Tr[r]  = g_wh1[i];
        G1r[r] = g_G1[i];
        G2r[r] = g_G2[i];
        sacc[r] = 0.f;
    }

    // MMA tiling: warp -> rows wi*16, cols wc*32
    const int wi = warp >> 2, wc = warp & 3;
    float d[4][4];
    #pragma unroll
    for (int n = 0; n < 4; n++)
        #pragma unroll
        for (int k = 0; k < 4; k++) d[n][k] = 0.f;

    const float* adjp = adj + (size_t)(i0 + wg * 4) * N_GENES + jp * 2;

    // prefetch registers (tile jt)
    float2 av[4], w2q, f1q, f2q;
    #pragma unroll
    for (int r = 0; r < 4; r++)
        av[r] = __ldg((const float2*)(adjp + (size_t)r * N_GENES));
    w2q = *(const float2*)&g_wh2[jp * 2];
    f1q = *(const float2*)&g_F1[jp * 2];
    f2q = *(const float2*)&g_F2[jp * 2];

    // prologue: cp.async V tile 0 into buf 0
    {
        #pragma unroll
        for (int u = 0; u < 2; u++) {
            const int idx = t + u * 512;
            const int row = idx >> 4, seg = idx & 15;
            const uint32_t dst = sb + SM_V0 + (seg >> 3) * 8192 + swz(row * 128 + (seg & 7) * 16);
            const __half* src = &g_whh[(size_t)row * OUT_DIM + seg * 8];
            asm volatile("cp.async.cg.shared.global [%0], [%1], 16;" :: "r"(dst), "l"(src));
        }
        asm volatile("cp.async.commit_group;" ::: "memory");
    }

    for (int jt = 0; jt < NT; jt++) {
        const int b = jt & 1;
        const uint32_t PB = sb + (b ? SM_P1 : SM_P0);
        const uint32_t VB = sb + (b ? SM_V1 : SM_V0);

        // ---- build P tile (4 rows x 2 cols per thread) into PB ----
        #pragma unroll
        for (int r = 0; r < 4; r++) {
            const float T = Tr[r], G1 = G1r[r], G2 = G2r[r];
            float x0 = T + w2q.x, x1 = T + w2q.y;
            float e0 = fmaxf(G1 * f1q.x, G2 * f2q.x);   // exp(lrelu(x)-B), monotone split
            float e1 = fmaxf(G1 * f1q.y, G2 * f2q.y);
            float p0 = (av[r].x != 0.f && x0 != 0.f) ? e0 : 0.f;
            float p1 = (av[r].y != 0.f && x1 != 0.f) ? e1 : 0.f;
            sacc[r] += p0 + p1;
            __half2 h = __floats2half2_rn(p0, p1);
            const uint32_t a = PB + swz((wg * 4 + r) * 128 + jp * 4);
            asm volatile("st.shared.b32 [%0], %1;" :: "r"(a), "r"(*(uint32_t*)&h));
        }

        // ---- prefetch next tile's adj + factor regs ----
        if (jt + 1 < NT) {
            const int jo = (jt + 1) * TJ;
            #pragma unroll
            for (int r = 0; r < 4; r++)
                av[r] = __ldg((const float2*)(adjp + (size_t)r * N_GENES + jo));
            w2q = *(const float2*)&g_wh2[jo + jp * 2];
            f1q = *(const float2*)&g_F1[jo + jp * 2];
            f2q = *(const float2*)&g_F2[jo + jp * 2];
        }

        // V[b] must be resident; P[b] written by all warps
        asm volatile("cp.async.wait_group 0;" ::: "memory");
        __syncthreads();

        // ---- issue cp.async for V[b^1] (tile jt+1); safe: reads of b^1 done pre-barrier ----
        if (jt + 1 < NT) {
            const int jo = (jt + 1) * TJ;
            const uint32_t VB2 = sb + ((b ^ 1) ? SM_V1 : SM_V0);
            #pragma unroll
            for (int u = 0; u < 2; u++) {
                const int idx = t + u * 512;
                const int row = idx >> 4, seg = idx & 15;
                const uint32_t dst = VB2 + (seg >> 3) * 8192 + swz(row * 128 + (seg & 7) * 16);
                const __half* src = &g_whh[(size_t)(jo + row) * OUT_DIM + seg * 8];
                asm volatile("cp.async.cg.shared.global [%0], [%1], 16;" :: "r"(dst), "l"(src));
            }
            asm volatile("cp.async.commit_group;" ::: "memory");
        }

        // ---- MMA: D(16x32 per warp) += P(16x64) @ V(64x32) ----
        #pragma unroll
        for (int ks = 0; ks < 4; ks++) {
            uint32_t a0, a1, a2, a3;
            const uint32_t aaddr = PB + swz((wi * 16 + (lane & 15)) * 128 + ks * 32 + (lane >> 4) * 16);
            asm volatile("ldmatrix.sync.aligned.m8n8.x4.shared.b16 {%0,%1,%2,%3},[%4];\n"
                         : "=r"(a0), "=r"(a1), "=r"(a2), "=r"(a3) : "r"(aaddr));
            uint32_t bfr[8];
            const int atom = wc >> 1;
            const int cin0 = (wc & 1) * 32 + (lane >> 4) * 8;
            const uint32_t brow = (ks * 16 + (lane & 15)) * 128;
            const uint32_t baddr0 = VB + atom * 8192 + swz(brow + cin0 * 2);
            asm volatile("ldmatrix.sync.aligned.m8n8.x4.trans.shared.b16 {%0,%1,%2,%3},[%4];\n"
                         : "=r"(bfr[0]), "=r"(bfr[1]), "=r"(bfr[2]), "=r"(bfr[3]) : "r"(baddr0));
            const uint32_t baddr1 = VB + atom * 8192 + swz(brow + (cin0 + 16) * 2);
            asm volatile("ldmatrix.sync.aligned.m8n8.x4.trans.shared.b16 {%0,%1,%2,%3},[%4];\n"
                         : "=r"(bfr[4]), "=r"(bfr[5]), "=r"(bfr[6]), "=r"(bfr[7]) : "r"(baddr1));
            #pragma unroll
            for (int n = 0; n < 4; n++) {
                asm volatile(
                    "mma.sync.aligned.m16n8k16.row.col.f32.f16.f16.f32 "
                    "{%0,%1,%2,%3},{%4,%5,%6,%7},{%8,%9},{%0,%1,%2,%3};\n"
                    : "+f"(d[n][0]), "+f"(d[n][1]), "+f"(d[n][2]), "+f"(d[n][3])
                    : "r"(a0), "r"(a1), "r"(a2), "r"(a3), "r"(bfr[n * 2]), "r"(bfr[n * 2 + 1]));
            }
        }
    }

    // ---- S: full-warp reduce over 32 column-pairs -> rows wg*4+r ----
    #pragma unroll
    for (int r = 0; r < 4; r++) {
        float v = sacc[r];
        #pragma unroll
        for (int o = 16; o; o >>= 1) v += __shfl_xor_sync(0xffffffffu, v, o);
        if (lane == 0) sS[wg * 4 + r] = v;
    }
    __syncthreads();
    if (t < TI) sS[t] = 1.0f / sS[t];
    __syncthreads();

    // ---- epilogue: normalize + ELU, direct store ----
    const int r1 = wi * 16 + (lane >> 2);
    const float inv1 = sS[r1], inv2 = sS[r1 + 8];
    #pragma unroll
    for (int n = 0; n < 4; n++) {
        const int c = wc * 32 + n * 8 + (lane & 3) * 2;
        float v00 = d[n][0] * inv1, v01 = d[n][1] * inv1;
        float v10 = d[n][2] * inv2, v11 = d[n][3] * inv2;
        float2 o1, o2;
        o1.x = v00 > 0.f ? v00 : expm1f(v00);
        o1.y = v01 > 0.f ? v01 : expm1f(v01);
        o2.x = v10 > 0.f ? v10 : expm1f(v10);
        o2.y = v11 > 0.f ? v11 : expm1f(v11);
        *(float2*)&out[(size_t)(i0 + r1) * OUT_DIM + c]     = o1;
        *(float2*)&out[(size_t)(i0 + r1 + 8) * OUT_DIM + c] = o2;
    }
}

// ---------------- launch ----------------
extern "C" void kernel_launch(void* const* d_in, const int* in_sizes, int n_in,
                              void* d_out, int out_size) {
    const float* inp = (const float*)d_in[0];   // [16384, 256]
    const float* adj = (const float*)d_in[1];   // [8192, 16384]
    const float* W   = (const float*)d_in[2];   // [256, 128]
    const float* a   = (const float*)d_in[3];   // [256, 1]
    float* out = (float*)d_out;                 // [8192, 128]

    cudaFuncSetAttribute(k_attn, cudaFuncAttributeMaxDynamicSharedMemorySize, SMEM_BYTES);

    k_transW <<<D_MODEL, OUT_DIM>>>(W);
    k_gemm1  <<<N_GENES / 8, 128>>>(inp);
    k_wh12   <<<N_GENES / 8, 256>>>(a);
    k_max    <<<1, 1024>>>();
    k_factors<<<N_GENES / 256, 256>>>();
    k_attn   <<<N_REG / TI, 512, SMEM_BYTES>>>(adj, out);
}

// round 4
// speedup vs baseline: 1.1495x; 1.1441x over previous
#include <cuda_runtime.h>
#include <cuda_fp16.h>
#include <cstdint>

#define N_GENES 16384
#define N_REG   8192
#define D_MODEL 256
#define OUT_DIM 128
#define ALPHA   0.2f

#define TI 64                  // regulon rows per CTA
#define TJ 64                  // j per tile (MMA K)
#define NT (N_GENES / TJ)      // 256 tiles
#define STAGES 4

// smem layout
#define SM_P    0                      // 2 x 8 KB P double buffer
#define SM_ADJ  16384                  // 4 x 16 KB adj stages (raw fp32 rows, 256 B/row)
#define SM_V    81920                  // 4 x 16 KB V stages (fp16, swizzled 2x64-col atoms)
#define SM_S    147456                 // 64 floats
#define SMEM_BYTES 147712

// ---------------- device scratch ----------------
__device__ float  g_wh [N_GENES * OUT_DIM];
__device__ __align__(16) __half g_whh[N_GENES * OUT_DIM];   // w_h fp16, row-major
__device__ float  g_WT [OUT_DIM * D_MODEL];
__device__ float  g_wh1[N_REG];
__device__ float  g_wh2[N_GENES];
__device__ float  g_F1 [N_GENES];
__device__ float  g_F2 [N_GENES];
__device__ float  g_G1 [N_REG];
__device__ float  g_G2 [N_REG];
__device__ float  g_w2max;

// ---------------- helpers ----------------
static __device__ __forceinline__ uint32_t swz(uint32_t x) { return x ^ ((x >> 3) & 0x70); }
static __device__ __forceinline__ uint32_t smem_u32(const void* p) {
    return (uint32_t)__cvta_generic_to_shared(p);
}
static __device__ __forceinline__ uint64_t pk2(float x, float y) {
    uint64_t r; asm("mov.b64 %0, {%1, %2};" : "=l"(r) : "f"(x), "f"(y)); return r;
}
static __device__ __forceinline__ void fma2(uint64_t& acc, uint64_t a, uint64_t b) {
    asm volatile("fma.rn.f32x2 %0, %1, %2, %0;" : "+l"(acc) : "l"(a), "l"(b));
}

// ---------------- K0: W transpose ----------------
__global__ void k_transW(const float* __restrict__ W) {
    g_WT[threadIdx.x * D_MODEL + blockIdx.x] = W[blockIdx.x * OUT_DIM + threadIdx.x];
}

// ---------------- K1: w_h = input @ weights ----------------
__global__ void k_gemm1(const float* __restrict__ inp) {
    __shared__ __align__(16) float s_in[8][D_MODEL];
    const int c  = threadIdx.x;
    const int r0 = blockIdx.x * 8;
    for (int idx = c; idx < 8 * D_MODEL; idx += 128)
        s_in[idx >> 8][idx & 255] = inp[(size_t)(r0 + (idx >> 8)) * D_MODEL + (idx & 255)];
    __syncthreads();

    uint64_t acc[8];
    #pragma unroll
    for (int r = 0; r < 8; r++) acc[r] = 0ull;

    const float4* wt4 = (const float4*)&g_WT[c * D_MODEL];
    #pragma unroll 2
    for (int k4 = 0; k4 < D_MODEL / 4; k4++) {
        float4 wv = __ldg(&wt4[k4]);
        uint64_t w01 = pk2(wv.x, wv.y);
        uint64_t w23 = pk2(wv.z, wv.w);
        #pragma unroll
        for (int r = 0; r < 8; r++) {
            ulonglong2 a2 = *(const ulonglong2*)&s_in[r][k4 * 4];
            fma2(acc[r], a2.x, w01);
            fma2(acc[r], a2.y, w23);
        }
    }
    #pragma unroll
    for (int r = 0; r < 8; r++) {
        float lo = __uint_as_float((uint32_t)acc[r]);
        float hi = __uint_as_float((uint32_t)(acc[r] >> 32));
        float v = lo + hi;
        g_wh [(size_t)(r0 + r) * OUT_DIM + c] = v;
        g_whh[(size_t)(r0 + r) * OUT_DIM + c] = __float2half(v);
    }
}

// ---------------- K2: wh1, wh2 ----------------
__global__ void k_wh12(const float* __restrict__ a) {
    const int row  = blockIdx.x * 8 + (threadIdx.x >> 5);
    const int lane = threadIdx.x & 31;
    const float* r = g_wh + (size_t)row * OUT_DIM;
    float s1 = 0.f, s2 = 0.f;
    #pragma unroll
    for (int c = lane; c < OUT_DIM; c += 32) {
        float v = r[c];
        s1 = fmaf(v, a[c], s1);
        s2 = fmaf(v, a[OUT_DIM + c], s2);
    }
    #pragma unroll
    for (int o = 16; o; o >>= 1) {
        s1 += __shfl_xor_sync(0xffffffffu, s1, o);
        s2 += __shfl_xor_sync(0xffffffffu, s2, o);
    }
    if (lane == 0) {
        if (row < N_REG) g_wh1[row] = s1;
        g_wh2[row] = s2;
    }
}

// ---------------- K3: max over wh2 ----------------
__global__ void k_max() {
    __shared__ float sm[32];
    float m = -1e30f;
    for (int j = threadIdx.x; j < N_GENES; j += blockDim.x) m = fmaxf(m, g_wh2[j]);
    #pragma unroll
    for (int o = 16; o; o >>= 1) m = fmaxf(m, __shfl_xor_sync(0xffffffffu, m, o));
    if ((threadIdx.x & 31) == 0) sm[threadIdx.x >> 5] = m;
    __syncthreads();
    if (threadIdx.x < 32) {
        float v = (threadIdx.x < (blockDim.x >> 5)) ? sm[threadIdx.x] : -1e30f;
        #pragma unroll
        for (int o = 16; o; o >>= 1) v = fmaxf(v, __shfl_xor_sync(0xffffffffu, v, o));
        if (threadIdx.x == 0) g_w2max = v;
    }
}

// ---------------- K4: exp factor tables ----------------
__global__ void k_factors() {
    const int j = blockIdx.x * 256 + threadIdx.x;
    const float w2m = g_w2max;
    if (j < N_GENES) {
        float w2 = g_wh2[j];
        g_F1[j] = expf(w2);
        g_F2[j] = expf(ALPHA * w2);
    }
    if (j < N_REG) {
        float w1 = g_wh1[j];
        float x  = w1 + w2m;
        float B  = x > 0.f ? x : ALPHA * x;
        g_G1[j] = expf(w1 - B);
        g_G2[j] = expf(ALPHA * w1 - B);
    }
}

// ---------------- K5: fused masked-softmax attention (deep cp.async pipeline) ----------------
__global__ void __launch_bounds__(512, 1)
k_attn(const float* __restrict__ adj, float* __restrict__ out) {
    extern __shared__ char smem[];
    const uint32_t sb = smem_u32(smem);
    float* sS = (float*)(smem + SM_S);

    const int t    = threadIdx.x;
    const int lane = t & 31, warp = t >> 5;
    const int i0   = blockIdx.x * TI;
    const int jp   = lane;            // column pair: cols jp*2, jp*2+1
    const int wg   = warp;            // P-build rows wg*4 .. wg*4+3

    // stage-load lane mapping (shared by adj and V loads)
    const int l_row = t >> 4;          // 0..31 -> rows t>>4 and (t+512)>>4
    const int l_ch  = t & 15;          // 16-byte chunk

    const float* adjbase = adj + (size_t)i0 * N_GENES;

    // issue one full stage (adj 16 KB + V 16 KB) for tile jt into ring slot st
    auto load_stage = [&](int jt) {
        const int st = jt & (STAGES - 1);
        const int jo = jt * TJ;
        const uint32_t AB = sb + SM_ADJ + st * 16384;
        const uint32_t VB = sb + SM_V   + st * 16384;
        #pragma unroll
        for (int u = 0; u < 2; u++) {
            const int row = l_row + u * 32;
            // adj: row stride 256 B in smem, raw
            const float* asrc = adjbase + (size_t)row * N_GENES + jo + l_ch * 4;
            asm volatile("cp.async.cg.shared.global [%0], [%1], 16;"
                         :: "r"(AB + row * 256 + l_ch * 16), "l"(asrc));
            // V: two 64-col swizzled atoms of 8 KB
            const __half* vsrc = &g_whh[(size_t)(jo + row) * OUT_DIM + l_ch * 8];
            const uint32_t vdst = VB + (l_ch >> 3) * 8192 + swz(row * 128 + (l_ch & 7) * 16);
            asm volatile("cp.async.cg.shared.global [%0], [%1], 16;" :: "r"(vdst), "l"(vsrc));
        }
        asm volatile("cp.async.commit_group;" ::: "memory");
    };

    // per-thread row constants for P build (4 rows)
    float Tr[4], G1r[4], G2r[4], sacc[4];
    #pragma unroll
    for (int r = 0; r < 4; r++) {
        const int i = i0 + wg * 4 + r;
        Tr[r]  = g_wh1[i];
        G1r[r] = g_G1[i];
        G2r[r] = g_G2[i];
        sacc[r] = 0.f;
    }

    // MMA tiling: warp -> rows wi*16, cols wc*32
    const int wi = warp >> 2, wc = warp & 3;
    float d[4][4];
    #pragma unroll
    for (int n = 0; n < 4; n++)
        #pragma unroll
        for (int k = 0; k < 4; k++) d[n][k] = 0.f;

    // prologue: fill 3 stages
    load_stage(0);
    load_stage(1);
    load_stage(2);

    for (int jt = 0; jt < NT; jt++) {
        const int st = jt & (STAGES - 1);
        const uint32_t PB = sb + SM_P + (jt & 1) * 8192;
        const uint32_t AB = sb + SM_ADJ + st * 16384;
        const uint32_t VB = sb + SM_V   + st * 16384;

        // stage jt must be resident (up to 3 groups in flight)
        asm volatile("cp.async.wait_group 2;" ::: "memory");
        __syncthreads();   // V[st]/adj[st] visible to all; P[b] free (readers done last iter)

        // issue stage jt+3 (overwrites slot (jt-1)&3, whose readers finished pre-barrier)
        if (jt + 3 < NT) load_stage(jt + 3);

        // ---- build P tile (4 rows x 2 cols per thread) from smem adj ----
        const int jo = jt * TJ;
        const float2 w2q = *(const float2*)&g_wh2[jo + jp * 2];
        const float2 f1q = *(const float2*)&g_F1 [jo + jp * 2];
        const float2 f2q = *(const float2*)&g_F2 [jo + jp * 2];
        #pragma unroll
        for (int r = 0; r < 4; r++) {
            float2 a2;
            asm volatile("ld.shared.v2.f32 {%0,%1}, [%2];"
                         : "=f"(a2.x), "=f"(a2.y)
                         : "r"(AB + (wg * 4 + r) * 256 + jp * 8));
            const float T = Tr[r], G1 = G1r[r], G2 = G2r[r];
            float x0 = T + w2q.x, x1 = T + w2q.y;
            float e0 = fmaxf(G1 * f1q.x, G2 * f2q.x);   // exp(lrelu(x)-B), monotone split
            float e1 = fmaxf(G1 * f1q.y, G2 * f2q.y);
            float p0 = (a2.x != 0.f && x0 != 0.f) ? e0 : 0.f;
            float p1 = (a2.y != 0.f && x1 != 0.f) ? e1 : 0.f;
            sacc[r] += p0 + p1;
            __half2 h = __floats2half2_rn(p0, p1);
            asm volatile("st.shared.b32 [%0], %1;"
                         :: "r"(PB + swz((wg * 4 + r) * 128 + jp * 4)), "r"(*(uint32_t*)&h));
        }
        __syncthreads();   // P[b] complete

        // ---- MMA: D(16x32 per warp) += P(16x64) @ V(64x32) ----
        #pragma unroll
        for (int ks = 0; ks < 4; ks++) {
            uint32_t a0, a1, a2, a3;
            const uint32_t aaddr = PB + swz((wi * 16 + (lane & 15)) * 128 + ks * 32 + (lane >> 4) * 16);
            asm volatile("ldmatrix.sync.aligned.m8n8.x4.shared.b16 {%0,%1,%2,%3},[%4];\n"
                         : "=r"(a0), "=r"(a1), "=r"(a2), "=r"(a3) : "r"(aaddr));
            uint32_t bfr[8];
            const int atom = wc >> 1;
            const int cin0 = (wc & 1) * 32 + (lane >> 4) * 8;
            const uint32_t brow = (ks * 16 + (lane & 15)) * 128;
            const uint32_t baddr0 = VB + atom * 8192 + swz(brow + cin0 * 2);
            asm volatile("ldmatrix.sync.aligned.m8n8.x4.trans.shared.b16 {%0,%1,%2,%3},[%4];\n"
                         : "=r"(bfr[0]), "=r"(bfr[1]), "=r"(bfr[2]), "=r"(bfr[3]) : "r"(baddr0));
            const uint32_t baddr1 = VB + atom * 8192 + swz(brow + (cin0 + 16) * 2);
            asm volatile("ldmatrix.sync.aligned.m8n8.x4.trans.shared.b16 {%0,%1,%2,%3},[%4];\n"
                         : "=r"(bfr[4]), "=r"(bfr[5]), "=r"(bfr[6]), "=r"(bfr[7]) : "r"(baddr1));
            #pragma unroll
            for (int n = 0; n < 4; n++) {
                asm volatile(
                    "mma.sync.aligned.m16n8k16.row.col.f32.f16.f16.f32 "
                    "{%0,%1,%2,%3},{%4,%5,%6,%7},{%8,%9},{%0,%1,%2,%3};\n"
                    : "+f"(d[n][0]), "+f"(d[n][1]), "+f"(d[n][2]), "+f"(d[n][3])
                    : "r"(a0), "r"(a1), "r"(a2), "r"(a3), "r"(bfr[n * 2]), "r"(bfr[n * 2 + 1]));
            }
        }
    }

    // ---- S: full-warp reduce over 32 column-pairs -> rows wg*4+r ----
    #pragma unroll
    for (int r = 0; r < 4; r++) {
        float v = sacc[r];
        #pragma unroll
        for (int o = 16; o; o >>= 1) v += __shfl_xor_sync(0xffffffffu, v, o);
        if (lane == 0) sS[wg * 4 + r] = v;
    }
    __syncthreads();
    if (t < TI) sS[t] = 1.0f / sS[t];
    __syncthreads();

    // ---- epilogue: normalize + ELU, direct store ----
    const int r1 = wi * 16 + (lane >> 2);
    const float inv1 = sS[r1], inv2 = sS[r1 + 8];
    #pragma unroll
    for (int n = 0; n < 4; n++) {
        const int c = wc * 32 + n * 8 + (lane & 3) * 2;
        float v00 = d[n][0] * inv1, v01 = d[n][1] * inv1;
        float v10 = d[n][2] * inv2, v11 = d[n][3] * inv2;
        float2 o1, o2;
        o1.x = v00 > 0.f ? v00 : expm1f(v00);
        o1.y = v01 > 0.f ? v01 : expm1f(v01);
        o2.x = v10 > 0.f ? v10 : expm1f(v10);
        o2.y = v11 > 0.f ? v11 : expm1f(v11);
        *(float2*)&out[(size_t)(i0 + r1) * OUT_DIM + c]     = o1;
        *(float2*)&out[(size_t)(i0 + r1 + 8) * OUT_DIM + c] = o2;
    }
}

// ---------------- launch ----------------
extern "C" void kernel_launch(void* const* d_in, const int* in_sizes, int n_in,
                              void* d_out, int out_size) {
    const float* inp = (const float*)d_in[0];   // [16384, 256]
    const float* adj = (const float*)d_in[1];   // [8192, 16384]
    const float* W   = (const float*)d_in[2];   // [256, 128]
    const float* a   = (const float*)d_in[3];   // [256, 1]
    float* out = (float*)d_out;                 // [8192, 128]

    cudaFuncSetAttribute(k_attn, cudaFuncAttributeMaxDynamicSharedMemorySize, SMEM_BYTES);

    k_transW <<<D_MODEL, OUT_DIM>>>(W);
    k_gemm1  <<<N_GENES / 8, 128>>>(inp);
    k_wh12   <<<N_GENES / 8, 256>>>(a);
    k_max    <<<1, 1024>>>();
    k_factors<<<N_GENES / 256, 256>>>();
    k_attn   <<<N_REG / TI, 512, SMEM_BYTES>>>(adj, out);
}

// round 5
// speedup vs baseline: 1.4056x; 1.2228x over previous
#include <cuda_runtime.h>
#include <cuda_fp16.h>
#include <cstdint>

#define N_GENES 16384
#define N_REG   8192
#define D_MODEL 256
#define OUT_DIM 128
#define ALPHA   0.2f

#define TI 32                  // regulon rows per CTA
#define TJ 64                  // j per tile (MMA K)
#define NT (N_GENES / TJ)      // 256 tiles
#define STAGES 3

// smem layout (per CTA: 80.1 KB -> 2 CTAs/SM)
#define SM_P    0                      // 2 x 4 KB P double buffer
#define SM_ADJ  8192                   // 3 x 8 KB adj stages (raw fp32, 256 B/row)
#define SM_V    32768                  // 3 x 16 KB V stages (fp16, swizzled 2x64-col atoms)
#define SM_S    81920                  // 32 floats
#define SMEM_BYTES 82048

// ---------------- device scratch ----------------
__device__ float  g_wh [N_GENES * OUT_DIM];
__device__ __align__(16) __half g_whh[N_GENES * OUT_DIM];   // w_h fp16, row-major
__device__ float  g_WT [OUT_DIM * D_MODEL];
__device__ float  g_wh1[N_REG];
__device__ float  g_wh2[N_GENES];
__device__ float  g_F1 [N_GENES];
__device__ float  g_F2 [N_GENES];
__device__ float  g_G1 [N_REG];
__device__ float  g_G2 [N_REG];
__device__ float  g_w2max;

// ---------------- helpers ----------------
static __device__ __forceinline__ uint32_t swz(uint32_t x) { return x ^ ((x >> 3) & 0x70); }
static __device__ __forceinline__ uint32_t smem_u32(const void* p) {
    return (uint32_t)__cvta_generic_to_shared(p);
}
static __device__ __forceinline__ uint64_t pk2(float x, float y) {
    uint64_t r; asm("mov.b64 %0, {%1, %2};" : "=l"(r) : "f"(x), "f"(y)); return r;
}
static __device__ __forceinline__ void fma2(uint64_t& acc, uint64_t a, uint64_t b) {
    asm volatile("fma.rn.f32x2 %0, %1, %2, %0;" : "+l"(acc) : "l"(a), "l"(b));
}

// ---------------- K0: W transpose ----------------
__global__ void k_transW(const float* __restrict__ W) {
    g_WT[threadIdx.x * D_MODEL + blockIdx.x] = W[blockIdx.x * OUT_DIM + threadIdx.x];
}

// ---------------- K1: w_h = input @ weights ----------------
__global__ void k_gemm1(const float* __restrict__ inp) {
    __shared__ __align__(16) float s_in[8][D_MODEL];
    const int c  = threadIdx.x;
    const int r0 = blockIdx.x * 8;
    for (int idx = c; idx < 8 * D_MODEL; idx += 128)
        s_in[idx >> 8][idx & 255] = inp[(size_t)(r0 + (idx >> 8)) * D_MODEL + (idx & 255)];
    __syncthreads();

    uint64_t acc[8];
    #pragma unroll
    for (int r = 0; r < 8; r++) acc[r] = 0ull;

    const float4* wt4 = (const float4*)&g_WT[c * D_MODEL];
    #pragma unroll 2
    for (int k4 = 0; k4 < D_MODEL / 4; k4++) {
        float4 wv = __ldg(&wt4[k4]);
        uint64_t w01 = pk2(wv.x, wv.y);
        uint64_t w23 = pk2(wv.z, wv.w);
        #pragma unroll
        for (int r = 0; r < 8; r++) {
            ulonglong2 a2 = *(const ulonglong2*)&s_in[r][k4 * 4];
            fma2(acc[r], a2.x, w01);
            fma2(acc[r], a2.y, w23);
        }
    }
    #pragma unroll
    for (int r = 0; r < 8; r++) {
        float lo = __uint_as_float((uint32_t)acc[r]);
        float hi = __uint_as_float((uint32_t)(acc[r] >> 32));
        float v = lo + hi;
        g_wh [(size_t)(r0 + r) * OUT_DIM + c] = v;
        g_whh[(size_t)(r0 + r) * OUT_DIM + c] = __float2half(v);
    }
}

// ---------------- K2: wh1, wh2 ----------------
__global__ void k_wh12(const float* __restrict__ a) {
    const int row  = blockIdx.x * 8 + (threadIdx.x >> 5);
    const int lane = threadIdx.x & 31;
    const float* r = g_wh + (size_t)row * OUT_DIM;
    float s1 = 0.f, s2 = 0.f;
    #pragma unroll
    for (int c = lane; c < OUT_DIM; c += 32) {
        float v = r[c];
        s1 = fmaf(v, a[c], s1);
        s2 = fmaf(v, a[OUT_DIM + c], s2);
    }
    #pragma unroll
    for (int o = 16; o; o >>= 1) {
        s1 += __shfl_xor_sync(0xffffffffu, s1, o);
        s2 += __shfl_xor_sync(0xffffffffu, s2, o);
    }
    if (lane == 0) {
        if (row < N_REG) g_wh1[row] = s1;
        g_wh2[row] = s2;
    }
}

// ---------------- K3: max over wh2 ----------------
__global__ void k_max() {
    __shared__ float sm[32];
    float m = -1e30f;
    for (int j = threadIdx.x; j < N_GENES; j += blockDim.x) m = fmaxf(m, g_wh2[j]);
    #pragma unroll
    for (int o = 16; o; o >>= 1) m = fmaxf(m, __shfl_xor_sync(0xffffffffu, m, o));
    if ((threadIdx.x & 31) == 0) sm[threadIdx.x >> 5] = m;
    __syncthreads();
    if (threadIdx.x < 32) {
        float v = (threadIdx.x < (blockDim.x >> 5)) ? sm[threadIdx.x] : -1e30f;
        #pragma unroll
        for (int o = 16; o; o >>= 1) v = fmaxf(v, __shfl_xor_sync(0xffffffffu, v, o));
        if (threadIdx.x == 0) g_w2max = v;
    }
}

// ---------------- K4: exp factor tables ----------------
__global__ void k_factors() {
    const int j = blockIdx.x * 256 + threadIdx.x;
    const float w2m = g_w2max;
    if (j < N_GENES) {
        float w2 = g_wh2[j];
        g_F1[j] = expf(w2);
        g_F2[j] = expf(ALPHA * w2);
    }
    if (j < N_REG) {
        float w1 = g_wh1[j];
        float x  = w1 + w2m;
        float B  = x > 0.f ? x : ALPHA * x;
        g_G1[j] = expf(w1 - B);
        g_G2[j] = expf(ALPHA * w1 - B);
    }
}

// ---------------- K5: fused masked-softmax attention ----------------
__global__ void __launch_bounds__(256, 2)
k_attn(const float* __restrict__ adj, float* __restrict__ out) {
    extern __shared__ char smem[];
    const uint32_t sb = smem_u32(smem);
    float* sS = (float*)(smem + SM_S);

    const int t    = threadIdx.x;
    const int lane = t & 31, warp = t >> 5;   // 8 warps
    const int i0   = blockIdx.x * TI;
    const int jp   = lane;            // column pair: cols jp*2, jp*2+1
    const int wg   = warp;            // P-build rows wg*4 .. wg*4+3

    const float* adjbase = adj + (size_t)i0 * N_GENES;

    // issue one stage (adj 8 KB + V 16 KB) for tile jt; ALWAYS commits a group
    auto load_stage = [&](int jt) {
        if (jt < NT) {
            const int st = jt % STAGES;
            const int jo = jt * TJ;
            const uint32_t AB = sb + SM_ADJ + st * 8192;
            const uint32_t VB = sb + SM_V   + st * 16384;
            // adj: 32 rows x 256 B, 2 chunks per thread
            #pragma unroll
            for (int u = 0; u < 2; u++) {
                const int row = (t >> 4) + u * 16;
                const int ch  = t & 15;
                const float* asrc = adjbase + (size_t)row * N_GENES + jo + ch * 4;
                asm volatile("cp.async.cg.shared.global [%0], [%1], 16;"
                             :: "r"(AB + row * 256 + ch * 16), "l"(asrc));
            }
            // V: 64 rows x 256 B -> 2 swizzled 64-col atoms, 4 chunks per thread
            #pragma unroll
            for (int u = 0; u < 4; u++) {
                const int idx = t + u * 256;
                const int row = idx >> 4, seg = idx & 15;
                const __half* vsrc = &g_whh[(size_t)(jo + row) * OUT_DIM + seg * 8];
                const uint32_t vdst = VB + (seg >> 3) * 8192 + swz(row * 128 + (seg & 7) * 16);
                asm volatile("cp.async.cg.shared.global [%0], [%1], 16;" :: "r"(vdst), "l"(vsrc));
            }
        }
        asm volatile("cp.async.commit_group;" ::: "memory");
    };

    // per-thread row constants for P build (4 rows)
    float Tr[4], G1r[4], G2r[4], sacc[4];
    #pragma unroll
    for (int r = 0; r < 4; r++) {
        const int i = i0 + wg * 4 + r;
        Tr[r]  = g_wh1[i];
        G1r[r] = g_G1[i];
        G2r[r] = g_G2[i];
        sacc[r] = 0.f;
    }

    // MMA tiling: warp -> rows wi*16, cols wc*32 (2x4 warp grid)
    const int wi = warp >> 2, wc = warp & 3;
    float d[4][4];
    #pragma unroll
    for (int n = 0; n < 4; n++)
        #pragma unroll
        for (int k = 0; k < 4; k++) d[n][k] = 0.f;

    // prologue: fill 2 stages
    load_stage(0);
    load_stage(1);

    for (int jt = 0; jt < NT; jt++) {
        const int st = jt % STAGES;
        const uint32_t PB = sb + SM_P + (jt & 1) * 4096;
        const uint32_t AB = sb + SM_ADJ + st * 8192;
        const uint32_t VB = sb + SM_V   + st * 16384;

        // stage jt must be resident (1 newer group may stay in flight)
        asm volatile("cp.async.wait_group 1;" ::: "memory");
        __syncthreads();

        // issue stage jt+2 (slot freed by iter jt-1's readers, all pre-barrier)
        load_stage(jt + 2);

        // ---- build P tile (4 rows x 2 cols per thread) from smem adj ----
        const int jo = jt * TJ;
        const float2 w2q = *(const float2*)&g_wh2[jo + jp * 2];
        const float2 f1q = *(const float2*)&g_F1 [jo + jp * 2];
        const float2 f2q = *(const float2*)&g_F2 [jo + jp * 2];
        #pragma unroll
        for (int r = 0; r < 4; r++) {
            float2 a2;
            asm volatile("ld.shared.v2.f32 {%0,%1}, [%2];"
                         : "=f"(a2.x), "=f"(a2.y)
                         : "r"(AB + (wg * 4 + r) * 256 + jp * 8));
            const float T = Tr[r], G1 = G1r[r], G2 = G2r[r];
            float x0 = T + w2q.x, x1 = T + w2q.y;
            float e0 = fmaxf(G1 * f1q.x, G2 * f2q.x);   // exp(lrelu(x)-B), monotone split
            float e1 = fmaxf(G1 * f1q.y, G2 * f2q.y);
            float p0 = (a2.x != 0.f && x0 != 0.f) ? e0 : 0.f;
            float p1 = (a2.y != 0.f && x1 != 0.f) ? e1 : 0.f;
            sacc[r] += p0 + p1;
            __half2 h = __floats2half2_rn(p0, p1);
            asm volatile("st.shared.b32 [%0], %1;"
                         :: "r"(PB + swz((wg * 4 + r) * 128 + jp * 4)), "r"(*(uint32_t*)&h));
        }
        __syncthreads();   // P complete

        // ---- MMA: D(16x32 per warp) += P(16x64) @ V(64x32) ----
        #pragma unroll
        for (int ks = 0; ks < 4; ks++) {
            uint32_t a0, a1, a2, a3;
            const uint32_t aaddr = PB + swz((wi * 16 + (lane & 15)) * 128 + ks * 32 + (lane >> 4) * 16);
            asm volatile("ldmatrix.sync.aligned.m8n8.x4.shared.b16 {%0,%1,%2,%3},[%4];\n"
                         : "=r"(a0), "=r"(a1), "=r"(a2), "=r"(a3) : "r"(aaddr));
            uint32_t bfr[8];
            const int atom = wc >> 1;
            const int cin0 = (wc & 1) * 32 + (lane >> 4) * 8;
            const uint32_t brow = (ks * 16 + (lane & 15)) * 128;
            const uint32_t baddr0 = VB + atom * 8192 + swz(brow + cin0 * 2);
            asm volatile("ldmatrix.sync.aligned.m8n8.x4.trans.shared.b16 {%0,%1,%2,%3},[%4];\n"
                         : "=r"(bfr[0]), "=r"(bfr[1]), "=r"(bfr[2]), "=r"(bfr[3]) : "r"(baddr0));
            const uint32_t baddr1 = VB + atom * 8192 + swz(brow + (cin0 + 16) * 2);
            asm volatile("ldmatrix.sync.aligned.m8n8.x4.trans.shared.b16 {%0,%1,%2,%3},[%4];\n"
                         : "=r"(bfr[4]), "=r"(bfr[5]), "=r"(bfr[6]), "=r"(bfr[7]) : "r"(baddr1));
            #pragma unroll
            for (int n = 0; n < 4; n++) {
                asm volatile(
                    "mma.sync.aligned.m16n8k16.row.col.f32.f16.f16.f32 "
                    "{%0,%1,%2,%3},{%4,%5,%6,%7},{%8,%9},{%0,%1,%2,%3};\n"
                    : "+f"(d[n][0]), "+f"(d[n][1]), "+f"(d[n][2]), "+f"(d[n][3])
                    : "r"(a0), "r"(a1), "r"(a2), "r"(a3), "r"(bfr[n * 2]), "r"(bfr[n * 2 + 1]));
            }
        }
    }

    // ---- S: full-warp reduce over 32 column-pairs -> rows wg*4+r ----
    #pragma unroll
    for (int r = 0; r < 4; r++) {
        float v = sacc[r];
        #pragma unroll
        for (int o = 16; o; o >>= 1) v += __shfl_xor_sync(0xffffffffu, v, o);
        if (lane == 0) sS[wg * 4 + r] = v;
    }
    __syncthreads();
    if (t < TI) sS[t] = 1.0f / sS[t];
    __syncthreads();

    // ---- epilogue: normalize + ELU, direct store ----
    const int r1 = wi * 16 + (lane >> 2);
    const float inv1 = sS[r1], inv2 = sS[r1 + 8];
    #pragma unroll
    for (int n = 0; n < 4; n++) {
        const int c = wc * 32 + n * 8 + (lane & 3) * 2;
        float v00 = d[n][0] * inv1, v01 = d[n][1] * inv1;
        float v10 = d[n][2] * inv2, v11 = d[n][3] * inv2;
        float2 o1, o2;
        o1.x = v00 > 0.f ? v00 : expm1f(v00);
        o1.y = v01 > 0.f ? v01 : expm1f(v01);
        o2.x = v10 > 0.f ? v10 : expm1f(v10);
        o2.y = v11 > 0.f ? v11 : expm1f(v11);
        *(float2*)&out[(size_t)(i0 + r1) * OUT_DIM + c]     = o1;
        *(float2*)&out[(size_t)(i0 + r1 + 8) * OUT_DIM + c] = o2;
    }
}

// ---------------- launch ----------------
extern "C" void kernel_launch(void* const* d_in, const int* in_sizes, int n_in,
                              void* d_out, int out_size) {
    const float* inp = (const float*)d_in[0];   // [16384, 256]
    const float* adj = (const float*)d_in[1];   // [8192, 16384]
    const float* W   = (const float*)d_in[2];   // [256, 128]
    const float* a   = (const float*)d_in[3];   // [256, 1]
    float* out = (float*)d_out;                 // [8192, 128]

    cudaFuncSetAttribute(k_attn, cudaFuncAttributeMaxDynamicSharedMemorySize, SMEM_BYTES);

    k_transW <<<D_MODEL, OUT_DIM>>>(W);
    k_gemm1  <<<N_GENES / 8, 128>>>(inp);
    k_wh12   <<<N_GENES / 8, 256>>>(a);
    k_max    <<<1, 1024>>>();
    k_factors<<<N_GENES / 256, 256>>>();
    k_attn   <<<N_REG / TI, 256, SMEM_BYTES>>>(adj, out);
}